// round 2
// baseline (speedup 1.0000x reference)
#include <cuda_runtime.h>

#define IN_F   4096
#define OUT_F  4096
#define Q_INF  3968
#define N_OUTL 128
#define M_ROWS 8192
#define K_DIM  4096
#define N_DIM  4096

// 64 MB scratch for the materialized effective weight matrix W_eff[o][i]
// (__device__ global: allowed scratch, no runtime allocation).
__device__ float g_W[(size_t)OUT_F * IN_F];

// ---------------------------------------------------------------------------
// Prep: W_eff[n][i] = (c = inv_perm[i]) < Q_INF ? q_w[n][c]*alpha[n]
//                                               : fp_w[n][c - Q_INF]
// ---------------------------------------------------------------------------
__global__ void prep_weights_kernel(const float* __restrict__ qw,
                                    const float* __restrict__ fw,
                                    const float* __restrict__ alpha,
                                    const int*   __restrict__ invp) {
    int idx = blockIdx.x * blockDim.x + threadIdx.x;   // over OUT_F*IN_F
    int n = idx >> 12;          // / 4096
    int i = idx & 4095;
    int c = invp[i];
    float v;
    if (c < Q_INF) v = qw[n * Q_INF + c] * alpha[n];
    else           v = fw[n * N_OUTL + (c - Q_INF)];
    g_W[idx] = v;
}

// ---------------------------------------------------------------------------
// Packed f32x2 helpers (Blackwell 2x-rate fp32; only reachable via PTX)
// ---------------------------------------------------------------------------
typedef unsigned long long u64;

__device__ __forceinline__ u64 pk2(float lo, float hi) {
    u64 r;
    asm("mov.b64 %0, {%1, %2};" : "=l"(r) : "f"(lo), "f"(hi));
    return r;
}
__device__ __forceinline__ void fma2(u64& c, u64 a, u64 b) {
    asm("fma.rn.f32x2 %0, %1, %2, %0;" : "+l"(c) : "l"(a), "l"(b));
}
__device__ __forceinline__ void upk2(u64 v, float& lo, float& hi) {
    asm("mov.b64 {%0, %1}, %2;" : "=f"(lo), "=f"(hi) : "l"(v));
}

// ---------------------------------------------------------------------------
// GEMM: C[m][n] = sum_k A[m][k] * W_eff[n][k] + bias[n]
// Tile 128x128x16, 256 threads, 8x8 per thread, f32x2 packed accumulation.
// ---------------------------------------------------------------------------
__global__ __launch_bounds__(256, 2)
void gemm_f32x2_kernel(const float* __restrict__ A,
                       const float* __restrict__ bias,
                       float* __restrict__ C) {
    __shared__ float As[16][132];   // [k][m], pad 132 -> 2-way max conflict
    __shared__ float Bs[16][132];   // [k][n]

    const float* __restrict__ Bw = g_W;

    const int tid = threadIdx.x;
    const int bm  = blockIdx.y;
    const int bn  = blockIdx.x;

    // Global-load mapping: each thread loads rows (lr, lr+64), 4 k-values at lc.
    const int lr = tid >> 2;            // 0..63
    const int lc = (tid & 3) << 2;      // 0,4,8,12

    const float* Aptr = A  + (size_t)(bm * 128 + lr) * K_DIM + lc;
    const float* Bptr = Bw + (size_t)(bn * 128 + lr) * K_DIM + lc;

    // Compute mapping: 16x16 thread grid, 8x8 outputs each.
    const int tx  = tid & 15;
    const int ty  = tid >> 4;
    const int tm0 = ty * 8;
    const int tn0 = tx * 8;

    u64 acc[8][4];
    #pragma unroll
    for (int i = 0; i < 8; i++)
        #pragma unroll
        for (int j = 0; j < 4; j++) acc[i][j] = 0ull;

    // Prologue: fetch k-tile 0 into registers.
    float4 ra0 = *(const float4*)(Aptr);
    float4 ra1 = *(const float4*)(Aptr + (size_t)64 * K_DIM);
    float4 rb0 = *(const float4*)(Bptr);
    float4 rb1 = *(const float4*)(Bptr + (size_t)64 * K_DIM);

    const int NT = K_DIM / 16;   // 256 k-tiles
    for (int kt = 0; kt < NT; kt++) {
        // Store current tile to smem (transposed).
        As[lc + 0][lr]      = ra0.x; As[lc + 1][lr]      = ra0.y;
        As[lc + 2][lr]      = ra0.z; As[lc + 3][lr]      = ra0.w;
        As[lc + 0][lr + 64] = ra1.x; As[lc + 1][lr + 64] = ra1.y;
        As[lc + 2][lr + 64] = ra1.z; As[lc + 3][lr + 64] = ra1.w;
        Bs[lc + 0][lr]      = rb0.x; Bs[lc + 1][lr]      = rb0.y;
        Bs[lc + 2][lr]      = rb0.z; Bs[lc + 3][lr]      = rb0.w;
        Bs[lc + 0][lr + 64] = rb1.x; Bs[lc + 1][lr + 64] = rb1.y;
        Bs[lc + 2][lr + 64] = rb1.z; Bs[lc + 3][lr + 64] = rb1.w;
        __syncthreads();

        // Prefetch next k-tile into registers (overlaps with compute).
        if (kt + 1 < NT) {
            const float* Ap = Aptr + (size_t)(kt + 1) * 16;
            const float* Bp = Bptr + (size_t)(kt + 1) * 16;
            ra0 = *(const float4*)(Ap);
            ra1 = *(const float4*)(Ap + (size_t)64 * K_DIM);
            rb0 = *(const float4*)(Bp);
            rb1 = *(const float4*)(Bp + (size_t)64 * K_DIM);
        }

        // Compute 8x8 outer products over the 16 k-steps.
        #pragma unroll
        for (int k = 0; k < 16; k++) {
            float4 a0 = *(const float4*)&As[k][tm0];
            float4 a1 = *(const float4*)&As[k][tm0 + 4];
            float4 b0 = *(const float4*)&Bs[k][tn0];
            float4 b1 = *(const float4*)&Bs[k][tn0 + 4];

            u64 bb0 = pk2(b0.x, b0.y);
            u64 bb1 = pk2(b0.z, b0.w);
            u64 bb2 = pk2(b1.x, b1.y);
            u64 bb3 = pk2(b1.z, b1.w);

            float av[8] = {a0.x, a0.y, a0.z, a0.w, a1.x, a1.y, a1.z, a1.w};
            #pragma unroll
            for (int i = 0; i < 8; i++) {
                u64 ad = pk2(av[i], av[i]);
                fma2(acc[i][0], ad, bb0);
                fma2(acc[i][1], ad, bb1);
                fma2(acc[i][2], ad, bb2);
                fma2(acc[i][3], ad, bb3);
            }
        }
        __syncthreads();
    }

    // Epilogue: add bias, write 8x8 block with float4 stores.
    float bv[8];
    #pragma unroll
    for (int j = 0; j < 8; j++) bv[j] = bias[bn * 128 + tn0 + j];

    #pragma unroll
    for (int i = 0; i < 8; i++) {
        float o[8];
        #pragma unroll
        for (int j = 0; j < 4; j++) upk2(acc[i][j], o[2 * j], o[2 * j + 1]);
        size_t row = (size_t)(bm * 128 + tm0 + i) * N_DIM + bn * 128 + tn0;
        float4 o0 = make_float4(o[0] + bv[0], o[1] + bv[1], o[2] + bv[2], o[3] + bv[3]);
        float4 o1 = make_float4(o[4] + bv[4], o[5] + bv[5], o[6] + bv[6], o[7] + bv[7]);
        *(float4*)&C[row]     = o0;
        *(float4*)&C[row + 4] = o1;
    }
}

// ---------------------------------------------------------------------------
// Launch. Inputs (metadata order): input, q_weight, fp_weight, alpha_scale,
// bias, inv_col_perm. Output: float32 [B, S, OUT_F].
// ---------------------------------------------------------------------------
extern "C" void kernel_launch(void* const* d_in, const int* in_sizes, int n_in,
                              void* d_out, int out_size) {
    const float* input = (const float*)d_in[0];
    const float* qw    = (const float*)d_in[1];
    const float* fw    = (const float*)d_in[2];
    const float* alpha = (const float*)d_in[3];
    const float* bias  = (const float*)d_in[4];
    const int*   invp  = (const int*)  d_in[5];
    float* out = (float*)d_out;

    prep_weights_kernel<<<(OUT_F * IN_F) / 256, 256>>>(qw, fw, alpha, invp);

    dim3 grid(N_DIM / 128, M_ROWS / 128);   // (32, 64)
    gemm_f32x2_kernel<<<grid, 256>>>(input, bias, out);
}

// round 4
// speedup vs baseline: 2.3555x; 2.3555x over previous
#include <cuda_runtime.h>
#include <cuda_bf16.h>
#include <cstdint>
#include <cstddef>

#define K_DIM  4096
#define M_ROWS 8192
#define N_DIM  4096
#define Q_INF  3968
#define N_OUTL 128

// GEMM tiling
#define TM 256
#define TN 128
#define KC 32
#define NT (K_DIM / KC)           // 128 k-iterations
#define STAGES 4

// Stage smem layout (bytes)
#define OFF_AH 0
#define OFF_AL (16 * 1024)
#define OFF_BH (32 * 1024)
#define OFF_BL (40 * 1024)
#define STAGE_BYTES (48 * 1024)
#define SMEM_TOTAL (STAGES * STAGE_BYTES)   // 196608

// ---------------------------------------------------------------------------
// Device-global scratch (no runtime allocation)
// ---------------------------------------------------------------------------
__device__ __nv_bfloat16 g_Ahi[(size_t)M_ROWS * K_DIM];
__device__ __nv_bfloat16 g_Alo[(size_t)M_ROWS * K_DIM];
__device__ __nv_bfloat16 g_Whi[(size_t)N_DIM * K_DIM];
__device__ __nv_bfloat16 g_Wlo[(size_t)N_DIM * K_DIM];

// ---------------------------------------------------------------------------
// Base-target PTX helpers (NO sm_103a-gated instructions!)
// ---------------------------------------------------------------------------
__device__ __forceinline__ uint32_t smem_to_u32(const void* p) {
    uint32_t a;
    asm("{ .reg .u64 t; cvta.to.shared.u64 t, %1; cvt.u32.u64 %0, t; }"
        : "=r"(a) : "l"(p));
    return a;
}

__device__ __forceinline__ void cpa16(uint32_t dst, const void* src) {
    asm volatile("cp.async.cg.shared.global [%0], [%1], 16;"
                 :: "r"(dst), "l"(src) : "memory");
}

__device__ __forceinline__ void ldsm4(uint32_t* r, uint32_t addr) {
    asm volatile("ldmatrix.sync.aligned.m8n8.x4.shared.b16 {%0,%1,%2,%3}, [%4];"
                 : "=r"(r[0]), "=r"(r[1]), "=r"(r[2]), "=r"(r[3]) : "r"(addr));
}

__device__ __forceinline__ void mma16816(float* c, const uint32_t* a,
                                         uint32_t b0, uint32_t b1) {
    asm volatile(
        "mma.sync.aligned.m16n8k16.row.col.f32.bf16.bf16.f32 "
        "{%0,%1,%2,%3}, {%4,%5,%6,%7}, {%8,%9}, {%0,%1,%2,%3};"
        : "+f"(c[0]), "+f"(c[1]), "+f"(c[2]), "+f"(c[3])
        : "r"(a[0]), "r"(a[1]), "r"(a[2]), "r"(a[3]), "r"(b0), "r"(b1));
}

// Conflict-free tile layout: rows of 32 bf16 (64B) packed 2 rows/128B line,
// 16B granule g in [0,4) XOR-swizzled by line index. Verified: any 8-lane
// ldmatrix phase (8 consecutive rows, fixed g) covers all 32 banks.
__device__ __forceinline__ uint32_t tile_off(int row, int g) {
    int p = row >> 1;
    return (uint32_t)(p * 128 + (row & 1) * 64 + ((g ^ (p & 3)) * 16));
}

// ---------------------------------------------------------------------------
// Prep: fp32 -> bf16 hi/lo splits
// ---------------------------------------------------------------------------
__global__ void split_A_kernel(const float4* __restrict__ in) {
    size_t i = (size_t)blockIdx.x * blockDim.x + threadIdx.x;   // M*K/4
    float4 v = in[i];
    __nv_bfloat16 h0 = __float2bfloat16(v.x), h1 = __float2bfloat16(v.y);
    __nv_bfloat16 h2 = __float2bfloat16(v.z), h3 = __float2bfloat16(v.w);
    __nv_bfloat16 l0 = __float2bfloat16(v.x - __bfloat162float(h0));
    __nv_bfloat16 l1 = __float2bfloat16(v.y - __bfloat162float(h1));
    __nv_bfloat16 l2 = __float2bfloat16(v.z - __bfloat162float(h2));
    __nv_bfloat16 l3 = __float2bfloat16(v.w - __bfloat162float(h3));
    __nv_bfloat162* Hi = (__nv_bfloat162*)g_Ahi;
    __nv_bfloat162* Lo = (__nv_bfloat162*)g_Alo;
    Hi[2 * i]     = __halves2bfloat162(h0, h1);
    Hi[2 * i + 1] = __halves2bfloat162(h2, h3);
    Lo[2 * i]     = __halves2bfloat162(l0, l1);
    Lo[2 * i + 1] = __halves2bfloat162(l2, l3);
}

__global__ void prep_W_kernel(const float* __restrict__ qw,
                              const float* __restrict__ fw,
                              const float* __restrict__ alpha,
                              const int*   __restrict__ invp) {
    int idx = blockIdx.x * 256 + threadIdx.x;   // N*K
    int n = idx >> 12;
    int i = idx & 4095;
    int c = invp[i];
    float v = (c < Q_INF) ? qw[n * Q_INF + c] * alpha[n]
                          : fw[n * N_OUTL + (c - Q_INF)];
    __nv_bfloat16 h = __float2bfloat16(v);
    g_Whi[idx] = h;
    g_Wlo[idx] = __float2bfloat16(v - __bfloat162float(h));
}

// ---------------------------------------------------------------------------
// GEMM: C = A * W^T + bias via bf16x3 on mma.sync (HMMA).
// CTA 256x128, 8 warps (4m x 2n), warp tile 64x64, 4-stage cp.async pipeline.
// ---------------------------------------------------------------------------
__global__ __launch_bounds__(256, 1)
void gemm_hmma_kernel(const float* __restrict__ bias, float* __restrict__ C) {
    extern __shared__ char smem[];
    const uint32_t sbase = smem_to_u32(smem);
    const int tid = threadIdx.x;
    const int wid = tid >> 5;
    const int lid = tid & 31;
    const int wm  = wid >> 1;          // 0..3 -> m offset wm*64
    const int wn  = wid & 1;           // 0..1 -> n offset wn*64
    const int m0  = blockIdx.y * TM;
    const int n0  = blockIdx.x * TN;

    float acc[4][8][4];
    #pragma unroll
    for (int i = 0; i < 4; i++)
        #pragma unroll
        for (int j = 0; j < 8; j++)
            #pragma unroll
            for (int t = 0; t < 4; t++) acc[i][j][t] = 0.0f;

    // ---- stage loader: 12 cp.async x 16B per thread ----
    const int lrow = tid >> 2;          // 0..63
    const int lg   = tid & 3;           // granule 0..3 (16B each, 64B row)
    auto load_stage = [&](int slot, int k0) {
        const uint32_t stg = sbase + slot * STAGE_BYTES;
        #pragma unroll
        for (int i = 0; i < 4; i++) {   // A: 256 rows
            int row = lrow + i * 64;
            uint32_t o = tile_off(row, lg);
            const size_t gsrc = (size_t)(m0 + row) * K_DIM + k0 + lg * 8;
            cpa16(stg + OFF_AH + o, g_Ahi + gsrc);
            cpa16(stg + OFF_AL + o, g_Alo + gsrc);
        }
        #pragma unroll
        for (int i = 0; i < 2; i++) {   // B: 128 rows
            int row = lrow + i * 64;
            uint32_t o = tile_off(row, lg);
            const size_t gsrc = (size_t)(n0 + row) * K_DIM + k0 + lg * 8;
            cpa16(stg + OFF_BH + o, g_Whi + gsrc);
            cpa16(stg + OFF_BL + o, g_Wlo + gsrc);
        }
    };

    // ---- per-stage compute: 2 x k16 steps ----
    const int frow = lid & 15;
    const int fg   = lid >> 4;
    auto compute_stage = [&](int slot) {
        const uint32_t stg = sbase + slot * STAGE_BYTES;
        #pragma unroll
        for (int s = 0; s < 2; s++) {
            uint32_t ah[4][4], al[4][4], bh[4][4], bl[4][4];
            #pragma unroll
            for (int i = 0; i < 4; i++) {
                int row = wm * 64 + i * 16 + frow;
                uint32_t o = tile_off(row, 2 * s + fg);
                ldsm4(ah[i], stg + OFF_AH + o);
                ldsm4(al[i], stg + OFF_AL + o);
            }
            #pragma unroll
            for (int j = 0; j < 4; j++) {
                int row = wn * 64 + j * 16 + frow;
                uint32_t o = tile_off(row, 2 * s + fg);
                ldsm4(bh[j], stg + OFF_BH + o);
                ldsm4(bl[j], stg + OFF_BL + o);
            }
            #pragma unroll
            for (int i = 0; i < 4; i++)
                #pragma unroll
                for (int j = 0; j < 4; j++) {
                    // ah*bh + al*bh + ah*bl  (al*bl dropped, ~2^-18)
                    mma16816(acc[i][2 * j],     ah[i], bh[j][0], bh[j][2]);
                    mma16816(acc[i][2 * j + 1], ah[i], bh[j][1], bh[j][3]);
                    mma16816(acc[i][2 * j],     al[i], bh[j][0], bh[j][2]);
                    mma16816(acc[i][2 * j + 1], al[i], bh[j][1], bh[j][3]);
                    mma16816(acc[i][2 * j],     ah[i], bl[j][0], bl[j][2]);
                    mma16816(acc[i][2 * j + 1], ah[i], bl[j][1], bl[j][3]);
                }
        }
    };

    // ---- pipeline ----
    #pragma unroll
    for (int s = 0; s < STAGES - 1; s++) {
        load_stage(s, s * KC);
        asm volatile("cp.async.commit_group;" ::: "memory");
    }
    for (int kt = 0; kt < NT; kt++) {
        asm volatile("cp.async.wait_group 2;" ::: "memory");
        __syncthreads();
        const int nx = kt + STAGES - 1;
        if (nx < NT) load_stage(nx & (STAGES - 1), nx * KC);
        asm volatile("cp.async.commit_group;" ::: "memory");
        compute_stage(kt & (STAGES - 1));
        // no trailing sync needed: next iter's top sync orders slot reuse
    }

    // ---- epilogue: bias + float2 stores straight from c-fragments ----
    const int qid = lid >> 2;       // fragment row within 8
    const int tq  = lid & 3;        // fragment col pair
    #pragma unroll
    for (int i = 0; i < 4; i++) {
        const int mrow = m0 + wm * 64 + i * 16 + qid;
        #pragma unroll
        for (int j2 = 0; j2 < 8; j2++) {
            const int nc = n0 + wn * 64 + j2 * 8 + 2 * tq;
            const float b0 = bias[nc], b1 = bias[nc + 1];
            float2 v0 = make_float2(acc[i][j2][0] + b0, acc[i][j2][1] + b1);
            float2 v1 = make_float2(acc[i][j2][2] + b0, acc[i][j2][3] + b1);
            *(float2*)&C[(size_t)mrow * N_DIM + nc]       = v0;
            *(float2*)&C[(size_t)(mrow + 8) * N_DIM + nc] = v1;
        }
    }
}

// ---------------------------------------------------------------------------
// Launch. Inputs: input, q_weight, fp_weight, alpha_scale, bias, inv_col_perm.
// ---------------------------------------------------------------------------
extern "C" void kernel_launch(void* const* d_in, const int* in_sizes, int n_in,
                              void* d_out, int out_size) {
    const float* input = (const float*)d_in[0];
    const float* qw    = (const float*)d_in[1];
    const float* fw    = (const float*)d_in[2];
    const float* alpha = (const float*)d_in[3];
    const float* bias  = (const float*)d_in[4];
    const int*   invp  = (const int*)  d_in[5];
    float* out = (float*)d_out;

    split_A_kernel<<<(M_ROWS * (K_DIM / 4)) / 256, 256>>>((const float4*)input);
    prep_W_kernel<<<(N_DIM * K_DIM) / 256, 256>>>(qw, fw, alpha, invp);

    static bool attr_set = false;
    if (!attr_set) {
        cudaFuncSetAttribute(gemm_hmma_kernel,
                             cudaFuncAttributeMaxDynamicSharedMemorySize, SMEM_TOTAL);
        attr_set = true;
    }
    dim3 grid(N_DIM / TN, M_ROWS / TM);   // (32, 32)
    gemm_hmma_kernel<<<grid, 256, SMEM_TOTAL>>>(bias, out);
}

// round 5
// speedup vs baseline: 3.2069x; 1.3615x over previous
#include <cuda_runtime.h>
#include <cuda_bf16.h>
#include <cstdint>
#include <cstddef>

#define K_DIM  4096
#define M_ROWS 8192
#define N_DIM  4096
#define KQ_DIM 3968            // exact-bf16 integer-weight part
#define N_OUTL 128

// GEMM tiling
#define TM 256
#define TN 128
#define KC 32
#define NT (K_DIM / KC)        // 128 k-iterations
#define NQ_IT (KQ_DIM / KC)    // 124 q-part iterations
#define STAGES 4

// Stage smem layout (bytes)
#define OFF_AH 0
#define OFF_AL (16 * 1024)
#define OFF_BH (32 * 1024)
#define OFF_BL (40 * 1024)
#define STAGE_BYTES (48 * 1024)
#define SMEM_TOTAL (STAGES * STAGE_BYTES)   // 196608

// ---------------------------------------------------------------------------
// Device-global scratch (no runtime allocation)
// ---------------------------------------------------------------------------
__device__ __nv_bfloat16 g_Ahi[(size_t)M_ROWS * K_DIM];   // permuted x, hi
__device__ __nv_bfloat16 g_Alo[(size_t)M_ROWS * K_DIM];   // permuted x, lo
__device__ __nv_bfloat16 g_Qb [(size_t)N_DIM * KQ_DIM];   // exact bf16 int weights
__device__ __nv_bfloat16 g_FPh[(size_t)N_DIM * N_OUTL];
__device__ __nv_bfloat16 g_FPl[(size_t)N_DIM * N_OUTL];

// ---------------------------------------------------------------------------
// Base-target PTX helpers (no sm_103a-gated instructions)
// ---------------------------------------------------------------------------
__device__ __forceinline__ uint32_t smem_to_u32(const void* p) {
    uint32_t a;
    asm("{ .reg .u64 t; cvta.to.shared.u64 t, %1; cvt.u32.u64 %0, t; }"
        : "=r"(a) : "l"(p));
    return a;
}

__device__ __forceinline__ void cpa16(uint32_t dst, const void* src) {
    asm volatile("cp.async.cg.shared.global [%0], [%1], 16;"
                 :: "r"(dst), "l"(src) : "memory");
}

__device__ __forceinline__ void ldsm4(uint32_t* r, uint32_t addr) {
    asm volatile("ldmatrix.sync.aligned.m8n8.x4.shared.b16 {%0,%1,%2,%3}, [%4];"
                 : "=r"(r[0]), "=r"(r[1]), "=r"(r[2]), "=r"(r[3]) : "r"(addr));
}

__device__ __forceinline__ void mma16816(float* c, const uint32_t* a,
                                         uint32_t b0, uint32_t b1) {
    asm volatile(
        "mma.sync.aligned.m16n8k16.row.col.f32.bf16.bf16.f32 "
        "{%0,%1,%2,%3}, {%4,%5,%6,%7}, {%8,%9}, {%0,%1,%2,%3};"
        : "+f"(c[0]), "+f"(c[1]), "+f"(c[2]), "+f"(c[3])
        : "r"(a[0]), "r"(a[1]), "r"(a[2]), "r"(a[3]), "r"(b0), "r"(b1));
}

// Conflict-free tile layout (verified in R4): rows of 32 bf16 (64B), 2 rows
// per 128B line, 16B granule XOR-swizzled by line index.
__device__ __forceinline__ uint32_t tile_off(int row, int g) {
    int p = row >> 1;
    return (uint32_t)(p * 128 + (row & 1) * 64 + ((g ^ (p & 3)) * 16));
}

// ---------------------------------------------------------------------------
// Prep A: permute columns of x (xp[invp[c]] = x[c]) and split fp32 -> bf16
// hi/lo. One CTA per row; smem staging keeps GMEM reads AND writes coalesced.
// ---------------------------------------------------------------------------
__global__ __launch_bounds__(256)
void perm_split_A_kernel(const float* __restrict__ x,
                         const int* __restrict__ invp) {
    __shared__ float rs[K_DIM];
    const int m = blockIdx.x;
    const float* xr = x + (size_t)m * K_DIM;
    for (int j = threadIdx.x; j < K_DIM; j += 256)
        rs[invp[j]] = xr[j];                        // smem scatter
    __syncthreads();
    __nv_bfloat162* H = (__nv_bfloat162*)(g_Ahi + (size_t)m * K_DIM);
    __nv_bfloat162* L = (__nv_bfloat162*)(g_Alo + (size_t)m * K_DIM);
    for (int j2 = threadIdx.x; j2 < K_DIM / 2; j2 += 256) {
        float v0 = rs[2 * j2], v1 = rs[2 * j2 + 1];
        __nv_bfloat16 h0 = __float2bfloat16(v0), h1 = __float2bfloat16(v1);
        __nv_bfloat16 l0 = __float2bfloat16(v0 - __bfloat162float(h0));
        __nv_bfloat16 l1 = __float2bfloat16(v1 - __bfloat162float(h1));
        H[j2] = __halves2bfloat162(h0, h1);
        L[j2] = __halves2bfloat162(l0, l1);
    }
}

// Prep W: exact bf16 copy of integer q_weight (NO alpha), hi/lo split of fp_w.
__global__ void prep_Q_kernel(const float* __restrict__ qw) {
    size_t idx = (size_t)blockIdx.x * 256 + threadIdx.x;   // O*KQ_DIM
    g_Qb[idx] = __float2bfloat16(qw[idx]);                 // exact: ints in [-8,7]
}

__global__ void prep_FP_kernel(const float* __restrict__ fw) {
    size_t idx = (size_t)blockIdx.x * 256 + threadIdx.x;   // O*N_OUTL
    float v = fw[idx];
    __nv_bfloat16 h = __float2bfloat16(v);
    g_FPh[idx] = h;
    g_FPl[idx] = __float2bfloat16(v - __bfloat162float(h));
}

// ---------------------------------------------------------------------------
// GEMM: acc = xp[:, :3968] * q^T  (2-term, 124 iters)
//       acc *= alpha[n]
//       acc += xp[:, 3968:] * fp^T (3-term, 4 iters)
//       C = acc + bias
// CTA 256x128, 8 warps (4m x 2n), warp tile 64x64, 4-stage cp.async pipeline.
// ---------------------------------------------------------------------------
__global__ __launch_bounds__(256, 1)
void gemm_hmma_kernel(const float* __restrict__ alpha,
                      const float* __restrict__ bias,
                      float* __restrict__ C) {
    extern __shared__ char smem[];
    const uint32_t sbase = smem_to_u32(smem);
    const int tid = threadIdx.x;
    const int wid = tid >> 5;
    const int lid = tid & 31;
    const int wm  = wid >> 1;
    const int wn  = wid & 1;
    const int m0  = blockIdx.y * TM;
    const int n0  = blockIdx.x * TN;

    float acc[4][8][4];
    #pragma unroll
    for (int i = 0; i < 4; i++)
        #pragma unroll
        for (int j = 0; j < 8; j++)
            #pragma unroll
            for (int t = 0; t < 4; t++) acc[i][j][t] = 0.0f;

    // ---- stage loader ----
    const int lrow = tid >> 2;          // 0..63
    const int lg   = tid & 3;           // 16B granule within 64B row
    auto load_stage = [&](int slot, int kt) {
        const uint32_t stg = sbase + slot * STAGE_BYTES;
        const int k0 = kt * KC;
        #pragma unroll
        for (int i = 0; i < 4; i++) {   // A: 256 rows from permuted xp
            int row = lrow + i * 64;
            uint32_t o = tile_off(row, lg);
            const size_t gsrc = (size_t)(m0 + row) * K_DIM + k0 + lg * 8;
            cpa16(stg + OFF_AH + o, g_Ahi + gsrc);
            cpa16(stg + OFF_AL + o, g_Alo + gsrc);
        }
        if (kt < NQ_IT) {
            #pragma unroll
            for (int i = 0; i < 2; i++) {   // B: exact int weights (single tile)
                int row = lrow + i * 64;
                uint32_t o = tile_off(row, lg);
                cpa16(stg + OFF_BH + o,
                      g_Qb + (size_t)(n0 + row) * KQ_DIM + k0 + lg * 8);
            }
        } else {
            const int ko = k0 - KQ_DIM;     // 0..96
            #pragma unroll
            for (int i = 0; i < 2; i++) {   // B: fp outlier weights, hi+lo
                int row = lrow + i * 64;
                uint32_t o = tile_off(row, lg);
                const size_t gsrc = (size_t)(n0 + row) * N_OUTL + ko + lg * 8;
                cpa16(stg + OFF_BH + o, g_FPh + gsrc);
                cpa16(stg + OFF_BL + o, g_FPl + gsrc);
            }
        }
    };

    const int frow = lid & 15;
    const int fg   = lid >> 4;

    // q-part: 2 terms (xh*q + xl*q), B exact
    auto compute_q = [&](int slot) {
        const uint32_t stg = sbase + slot * STAGE_BYTES;
        #pragma unroll
        for (int s = 0; s < 2; s++) {
            uint32_t ah[4][4], al[4][4], bh[4][4];
            #pragma unroll
            for (int i = 0; i < 4; i++) {
                int row = wm * 64 + i * 16 + frow;
                uint32_t o = tile_off(row, 2 * s + fg);
                ldsm4(ah[i], stg + OFF_AH + o);
                ldsm4(al[i], stg + OFF_AL + o);
            }
            #pragma unroll
            for (int j = 0; j < 4; j++) {
                int row = wn * 64 + j * 16 + frow;
                uint32_t o = tile_off(row, 2 * s + fg);
                ldsm4(bh[j], stg + OFF_BH + o);
            }
            #pragma unroll
            for (int i = 0; i < 4; i++)
                #pragma unroll
                for (int j = 0; j < 4; j++) {
                    mma16816(acc[i][2 * j],     ah[i], bh[j][0], bh[j][2]);
                    mma16816(acc[i][2 * j + 1], ah[i], bh[j][1], bh[j][3]);
                    mma16816(acc[i][2 * j],     al[i], bh[j][0], bh[j][2]);
                    mma16816(acc[i][2 * j + 1], al[i], bh[j][1], bh[j][3]);
                }
        }
    };

    // outlier part: 3 terms (ah*bh + al*bh + ah*bl)
    auto compute_o = [&](int slot) {
        const uint32_t stg = sbase + slot * STAGE_BYTES;
        #pragma unroll
        for (int s = 0; s < 2; s++) {
            uint32_t ah[4][4], al[4][4], bh[4][4], bl[4][4];
            #pragma unroll
            for (int i = 0; i < 4; i++) {
                int row = wm * 64 + i * 16 + frow;
                uint32_t o = tile_off(row, 2 * s + fg);
                ldsm4(ah[i], stg + OFF_AH + o);
                ldsm4(al[i], stg + OFF_AL + o);
            }
            #pragma unroll
            for (int j = 0; j < 4; j++) {
                int row = wn * 64 + j * 16 + frow;
                uint32_t o = tile_off(row, 2 * s + fg);
                ldsm4(bh[j], stg + OFF_BH + o);
                ldsm4(bl[j], stg + OFF_BL + o);
            }
            #pragma unroll
            for (int i = 0; i < 4; i++)
                #pragma unroll
                for (int j = 0; j < 4; j++) {
                    mma16816(acc[i][2 * j],     ah[i], bh[j][0], bh[j][2]);
                    mma16816(acc[i][2 * j + 1], ah[i], bh[j][1], bh[j][3]);
                    mma16816(acc[i][2 * j],     al[i], bh[j][0], bh[j][2]);
                    mma16816(acc[i][2 * j + 1], al[i], bh[j][1], bh[j][3]);
                    mma16816(acc[i][2 * j],     ah[i], bl[j][0], bl[j][2]);
                    mma16816(acc[i][2 * j + 1], ah[i], bl[j][1], bl[j][3]);
                }
        }
    };

    const int tq = lid & 3;             // fragment col pair

    // ---- pipeline ----
    #pragma unroll
    for (int s = 0; s < STAGES - 1; s++) {
        load_stage(s, s);
        asm volatile("cp.async.commit_group;" ::: "memory");
    }
    for (int kt = 0; kt < NT; kt++) {
        asm volatile("cp.async.wait_group 2;" ::: "memory");
        __syncthreads();
        const int nx = kt + STAGES - 1;
        if (nx < NT) load_stage(nx & (STAGES - 1), nx);
        asm volatile("cp.async.commit_group;" ::: "memory");

        if (kt == NQ_IT) {
            // q-part done: apply per-output alpha to accumulators
            #pragma unroll
            for (int j2 = 0; j2 < 8; j2++) {
                const int nc = n0 + wn * 64 + j2 * 8 + 2 * tq;
                const float s0 = alpha[nc], s1 = alpha[nc + 1];
                #pragma unroll
                for (int i = 0; i < 4; i++) {
                    acc[i][j2][0] *= s0; acc[i][j2][1] *= s1;
                    acc[i][j2][2] *= s0; acc[i][j2][3] *= s1;
                }
            }
        }
        if (kt < NQ_IT) compute_q(kt & (STAGES - 1));
        else            compute_o(kt & (STAGES - 1));
    }

    // ---- epilogue: bias + float2 stores ----
    const int qid = lid >> 2;
    #pragma unroll
    for (int i = 0; i < 4; i++) {
        const int mrow = m0 + wm * 64 + i * 16 + qid;
        #pragma unroll
        for (int j2 = 0; j2 < 8; j2++) {
            const int nc = n0 + wn * 64 + j2 * 8 + 2 * tq;
            const float b0 = bias[nc], b1 = bias[nc + 1];
            float2 v0 = make_float2(acc[i][j2][0] + b0, acc[i][j2][1] + b1);
            float2 v1 = make_float2(acc[i][j2][2] + b0, acc[i][j2][3] + b1);
            *(float2*)&C[(size_t)mrow * N_DIM + nc]       = v0;
            *(float2*)&C[(size_t)(mrow + 8) * N_DIM + nc] = v1;
        }
    }
}

// ---------------------------------------------------------------------------
// Launch. Inputs: input, q_weight, fp_weight, alpha_scale, bias, inv_col_perm.
// ---------------------------------------------------------------------------
extern "C" void kernel_launch(void* const* d_in, const int* in_sizes, int n_in,
                              void* d_out, int out_size) {
    const float* input = (const float*)d_in[0];
    const float* qw    = (const float*)d_in[1];
    const float* fw    = (const float*)d_in[2];
    const float* alpha = (const float*)d_in[3];
    const float* bias  = (const float*)d_in[4];
    const int*   invp  = (const int*)  d_in[5];
    float* out = (float*)d_out;

    perm_split_A_kernel<<<M_ROWS, 256>>>(input, invp);
    prep_Q_kernel<<<(N_DIM * KQ_DIM) / 256, 256>>>(qw);
    prep_FP_kernel<<<(N_DIM * N_OUTL) / 256, 256>>>(fw);

    static bool attr_set = false;
    if (!attr_set) {
        cudaFuncSetAttribute(gemm_hmma_kernel,
                             cudaFuncAttributeMaxDynamicSharedMemorySize, SMEM_TOTAL);
        attr_set = true;
    }
    dim3 grid(N_DIM / TN, M_ROWS / TM);   // (32, 32)
    gemm_hmma_kernel<<<grid, 256, SMEM_TOTAL>>>(alpha, bias, out);
}